// round 1
// baseline (speedup 1.0000x reference)
#include <cuda_runtime.h>
#include <cstdint>

// Problem constants
#define BATCH 1024
#define SEQL  200
#define DIM   128

// Scratch (allocation-free rule: __device__ globals)
__device__ float g_buf[BATCH * DIM];
__device__ float ag_buf[BATCH * DIM];

// ---------------------------------------------------------------------------
// Kernel 1: g[b] = sum_l item_embedding[items[b,l]]
// grid = BATCH blocks, 128 threads (one per dim). Auto-detects int64 vs int32
// index storage (jax x64 flag ambiguity) from high-word pattern.
// ---------------------------------------------------------------------------
__global__ void __launch_bounds__(DIM) gather_sum_kernel(
    const float* __restrict__ emb,
    const void* __restrict__ items_raw)
{
    const int b = blockIdx.x;
    const int t = threadIdx.x;

    __shared__ int sidx[SEQL];
    __shared__ int mode64;

    if (t == 0) {
        // If storage is int64 (little-endian, values < 5e5), every odd int32
        // word of the first 16 elements is 0. For int32 storage the odd words
        // are random indices in [0, 500000) -> all-zero is impossible.
        const int* p = (const int*)items_raw;
        int ok = 1;
        #pragma unroll
        for (int i = 0; i < 16; i++) ok &= (p[2 * i + 1] == 0);
        mode64 = ok;
    }
    __syncthreads();

    if (mode64) {
        const long long* it = (const long long*)items_raw;
        for (int l = t; l < SEQL; l += DIM) sidx[l] = (int)it[(long long)b * SEQL + l];
    } else {
        const int* it = (const int*)items_raw;
        for (int l = t; l < SEQL; l += DIM) sidx[l] = it[b * SEQL + l];
    }
    __syncthreads();

    // 4 independent accumulator chains for MLP; loads are coalesced 512B rows.
    float a0 = 0.f, a1 = 0.f, a2 = 0.f, a3 = 0.f;
    #pragma unroll 4
    for (int l = 0; l < SEQL; l += 4) {
        a0 += emb[(size_t)sidx[l + 0] * DIM + t];
        a1 += emb[(size_t)sidx[l + 1] * DIM + t];
        a2 += emb[(size_t)sidx[l + 2] * DIM + t];
        a3 += emb[(size_t)sidx[l + 3] * DIM + t];
    }
    g_buf[b * DIM + t] = (a0 + a1) + (a2 + a3);
}

// ---------------------------------------------------------------------------
// Kernel 2: Y[1024,128] = Am[1024,1024] @ X[1024,128]
// grid = 128 blocks (BM=8 rows each, full N=128), block = (128, 2).
// threadIdx.y splits K into halves (8 warps/block = 2 warps/SMSP so the
// fp32 FFMA pipe reaches its 0.5 warp-op/cyc reciprocal throughput).
// A tile consumed via float4 LDS (uniform/broadcast): 12 LDS per 32 FFMA,
// keeping issue pressure under the FFMA budget.
// ---------------------------------------------------------------------------
__global__ void __launch_bounds__(256) gemm_1024x128_kernel(
    const float* __restrict__ Am,
    const float* __restrict__ X,
    float* __restrict__ Y)
{
    const int t    = threadIdx.x;   // 0..127 -> N column
    const int half = threadIdx.y;   // 0..1   -> K half
    const int bm   = blockIdx.x * 8;

    __shared__ __align__(16) float sG[2][32][DIM];  // 32 KB
    __shared__ __align__(16) float sA[2][8][32];    //  2 KB
    __shared__ float red[8][DIM];                   //  4 KB

    float acc[8];
    #pragma unroll
    for (int m = 0; m < 8; m++) acc[m] = 0.f;

    const int kbase = half * 512;

    for (int kc = 0; kc < 512; kc += 32) {
        const int k0 = kbase + kc;

        // Stage X chunk [32][128] (coalesced; X is L2-resident: 512 KB, read by all blocks)
        #pragma unroll
        for (int r = 0; r < 32; r++)
            sG[half][r][t] = X[(k0 + r) * DIM + t];

        // Stage A chunk [8][32]
        #pragma unroll
        for (int i = t; i < 256; i += DIM) {
            const int m = i >> 5, kk = i & 31;
            sA[half][m][kk] = Am[(bm + m) * 1024 + k0 + kk];
        }
        __syncthreads();

        #pragma unroll
        for (int kk = 0; kk < 32; kk += 4) {
            const float g0 = sG[half][kk + 0][t];
            const float g1 = sG[half][kk + 1][t];
            const float g2 = sG[half][kk + 2][t];
            const float g3 = sG[half][kk + 3][t];
            #pragma unroll
            for (int m = 0; m < 8; m++) {
                const float4 a4 = *reinterpret_cast<const float4*>(&sA[half][m][kk]);
                acc[m] = fmaf(a4.x, g0, acc[m]);
                acc[m] = fmaf(a4.y, g1, acc[m]);
                acc[m] = fmaf(a4.z, g2, acc[m]);
                acc[m] = fmaf(a4.w, g3, acc[m]);
            }
        }
        __syncthreads();
    }

    // Combine the two K halves
    if (half == 1) {
        #pragma unroll
        for (int m = 0; m < 8; m++) red[m][t] = acc[m];
    }
    __syncthreads();
    if (half == 0) {
        #pragma unroll
        for (int m = 0; m < 8; m++)
            Y[(bm + m) * DIM + t] = acc[m] + red[m][t];
    }
}

// ---------------------------------------------------------------------------
// Kernel 3: out[b] = selu(h[b]) / ||selu(h[b])||
// ---------------------------------------------------------------------------
__global__ void __launch_bounds__(DIM) epilogue_kernel(
    const float* __restrict__ H, float* __restrict__ out)
{
    const int b = blockIdx.x;
    const int t = threadIdx.x;

    const float SELU_SCALE = 1.0507009873554804934f;
    const float SELU_ALPHA = 1.6732632423543772848f;

    const float v = H[b * DIM + t];
    const float s = (v > 0.f) ? SELU_SCALE * v
                              : SELU_SCALE * SELU_ALPHA * (expf(v) - 1.f);

    float sq = s * s;
    #pragma unroll
    for (int o = 16; o; o >>= 1) sq += __shfl_xor_sync(0xFFFFFFFFu, sq, o);

    __shared__ float ws[4];
    if ((t & 31) == 0) ws[t >> 5] = sq;
    __syncthreads();
    const float tot = ws[0] + ws[1] + ws[2] + ws[3];

    out[b * DIM + t] = s * rsqrtf(tot);
}

// ---------------------------------------------------------------------------
// Launch: gather -> Ag = A@g -> H = D@Ag -> normalize(selu(H))
// (The attention / entmax path is analytically the identity on g: scores are
//  constant along L, entmax of a constant is uniform, and sum(p)*g = g.)
// ---------------------------------------------------------------------------
extern "C" void kernel_launch(void* const* d_in, const int* in_sizes, int n_in,
                              void* d_out, int out_size)
{
    const float* emb   = (const float*)d_in[0];  // [500000, 128]
    const void*  items = d_in[1];                // [1024, 200] int64 or int32
    const float* Amat  = (const float*)d_in[2];  // [1024, 1024]
    const float* Dmat  = (const float*)d_in[3];  // [1024, 1024]
    float* out = (float*)d_out;                  // [1024, 128]

    float* g;  cudaGetSymbolAddress((void**)&g,  g_buf);
    float* ag; cudaGetSymbolAddress((void**)&ag, ag_buf);

    gather_sum_kernel<<<BATCH, DIM>>>(emb, items);

    dim3 gblk(DIM, 2);
    gemm_1024x128_kernel<<<BATCH / 8, gblk>>>(Amat, g, ag);   // ag = A @ g
    gemm_1024x128_kernel<<<BATCH / 8, gblk>>>(Dmat, ag, g);   // g  = D @ ag

    epilogue_kernel<<<BATCH, DIM>>>(g, out);
}